// round 8
// baseline (speedup 1.0000x reference)
#include <cuda_runtime.h>
#include <cuda_bf16.h>
#include <math.h>
#include <stdint.h>

// Shapes: x[8,128,64,64] off_w[27,128,3,3] off_b[27] w[128,128,3,3] b[128]
//         gamma[128] beta[128] -> out[8,128,64,64] fp32

#define NB   8
#define NC   128
#define NH   64
#define NW   64
#define NHW  4096
#define NKT  9
#define NOFF 27
#define KDIM 1152   // 128*9

static __device__ float    g_om[NB * NOFF * NHW];  // offset-conv output
static __device__ uint32_t g_w2[NC * KDIM];        // w permuted [o][kt*128+ci], tf32 bits
static __device__ float    g_y[NB * NC * NHW];     // pre-BN conv output
static __device__ float    g_stats[2 * NC];        // per-channel sum, sumsq

// ---------------- helpers ---------------------------------------------------
__device__ __forceinline__ uint32_t f2tf32(float v) {
    uint32_t r;
    asm("cvt.rna.tf32.f32 %0, %1;" : "=r"(r) : "f"(v));
    return r;
}
__device__ __forceinline__ void mma_tf32(float4& d, const uint32_t a[4],
                                         const uint32_t b[2]) {
    asm volatile(
        "mma.sync.aligned.m16n8k8.row.col.f32.tf32.tf32.f32 "
        "{%0,%1,%2,%3}, {%4,%5,%6,%7}, {%8,%9}, {%0,%1,%2,%3};"
        : "+f"(d.x), "+f"(d.y), "+f"(d.z), "+f"(d.w)
        : "r"(a[0]), "r"(a[1]), "r"(a[2]), "r"(a[3]), "r"(b[0]), "r"(b[1]));
}
__device__ __forceinline__ void ffma2(unsigned long long& d,
                                      unsigned long long a,
                                      unsigned long long b) {
    asm volatile("fma.rn.f32x2 %0, %1, %2, %0;" : "+l"(d) : "l"(a), "l"(b));
}
__device__ __forceinline__ unsigned long long pack2(float lo, float hi) {
    unsigned long long r;
    asm("mov.b64 %0, {%1, %2};" : "=l"(r) : "f"(lo), "f"(hi));
    return r;
}
__device__ __forceinline__ float2 unpack2(unsigned long long v) {
    float2 r;
    asm("mov.b64 {%0, %1}, %2;" : "=f"(r.x), "=f"(r.y) : "l"(v));
    return r;
}

// SMEM layout (dynamic, byte offsets). Tiles stride 36 floats (conflict-free).
#define OFF_SUM  0         // 512
#define OFF_SSQ  512       // 512
#define OFF_BIAS 1024      // 512
#define OFF_CO   1536      // 9*128*8  = 9216  (ushort4 corner byte-offsets)
#define OFF_WQ   10752     // 9*128*16 = 18432 (float4 bilinear weights)
#define OFF_A0   29184     // 128*36*4 = 18432
#define OFF_A1   47616
#define OFF_W0   66048
#define OFF_W1   84480
#define SMEM_SZ  102912
#define TSTRIDE  36

// ---------------------------------------------------------------------------
// Kernel Z: zero stats + permute weights to [o][kt*128+ci], pre-convert tf32
// ---------------------------------------------------------------------------
__global__ void prep_kernel(const float* __restrict__ w) {
    if (blockIdx.x == 0 && threadIdx.x < 2 * NC) g_stats[threadIdx.x] = 0.0f;
    int n = NC * KDIM;
    for (int i = blockIdx.x * blockDim.x + threadIdx.x; i < n;
         i += gridDim.x * blockDim.x) {
        int o  = i / KDIM;
        int r  = i - o * KDIM;
        int kt = r >> 7;
        int ci = r & 127;
        g_w2[i] = f2tf32(w[o * KDIM + ci * 9 + kt]);
    }
}

// ---------------------------------------------------------------------------
// Kernel A: offset conv. 256 blocks (8h x 16w tiles), 4 channels / iteration.
// ---------------------------------------------------------------------------
__global__ __launch_bounds__(256) void off_conv_kernel(
    const float* __restrict__ x,
    const float* __restrict__ ow,
    const float* __restrict__ ob) {
    __shared__ float xt[4][10][18];
    __shared__ unsigned long long wdup[4 * 243];

    const int tid  = threadIdx.x;
    const int og   = tid >> 6;        // 0..3
    const int slot = tid & 63;
    const int lr   = slot >> 4;       // 0..3
    const int lc   = slot & 15;
    const int b    = blockIdx.z;
    const int by   = blockIdx.y;
    const int bx   = blockIdx.x;

    unsigned long long accp[7];
#pragma unroll
    for (int j = 0; j < 7; ++j) accp[j] = 0ull;

    for (int it = 0; it < 32; ++it) {
        const int ci0 = it << 2;
        __syncthreads();
        for (int i = tid; i < 720; i += 256) {
            int ci  = i / 180;
            int rem = i - ci * 180;
            int r   = rem / 18;
            int cp  = rem - r * 18;
            int gy  = by * 8 + r - 1;
            int gx  = bx * 16 + cp - 1;
            float v = 0.0f;
            if (gy >= 0 && gy < NH && gx >= 0 && gx < NW)
                v = __ldg(x + ((size_t)(b * NC + ci0 + ci) << 12) + (gy << 6) + gx);
            xt[ci][r][cp] = v;
        }
        for (int i = tid; i < 972; i += 256) {
            int ci  = i / 243;
            int rem = i - ci * 243;
            int o   = rem / 9;
            int t   = rem - o * 9;
            float wv = __ldg(ow + (size_t)o * KDIM + (ci0 + ci) * 9 + t);
            wdup[i] = pack2(wv, wv);
        }
        __syncthreads();

#pragma unroll
        for (int ci = 0; ci < 4; ++ci) {
            unsigned long long xp[9];
#pragma unroll
            for (int dy = 0; dy < 3; ++dy)
#pragma unroll
                for (int dx = 0; dx < 3; ++dx)
                    xp[dy * 3 + dx] = pack2(xt[ci][lr + dy][lc + dx],
                                            xt[ci][lr + 4 + dy][lc + dx]);
#pragma unroll
            for (int j = 0; j < 7; ++j) {
                int o = og * 7 + j;
                if (o < NOFF) {
#pragma unroll
                    for (int t = 0; t < 9; ++t)
                        ffma2(accp[j], xp[t], wdup[ci * 243 + o * 9 + t]);
                }
            }
        }
    }

    const int gy0 = by * 8 + lr;
    const int gx  = bx * 16 + lc;
#pragma unroll
    for (int j = 0; j < 7; ++j) {
        int o = og * 7 + j;
        if (o < NOFF) {
            float bb = __ldg(ob + o);
            float2 a = unpack2(accp[j]);
            g_om[((size_t)(b * NOFF + o) << 12) + (gy0 << 6) + gx]       = a.x + bb;
            g_om[((size_t)(b * NOFF + o) << 12) + ((gy0 + 4) << 6) + gx] = a.y + bb;
        }
    }
}

// ---------------------------------------------------------------------------
// Kernel B: deformable sampling + mma.sync tf32 implicit GEMM + BN stats.
// kt-major K. Double-buffered tiles, 1 sync/chunk. FORCED 2 blocks/SM.
// ---------------------------------------------------------------------------
__global__ __launch_bounds__(256, 2) void dcn_main_kernel(
    const float* __restrict__ x,
    const float* __restrict__ bias) {
    extern __shared__ char smem[];
    const int tid  = threadIdx.x;
    const int wid  = tid >> 5;
    const int lane = tid & 31;
    const int wr   = wid >> 2;
    const int wc   = wid & 3;
    const int fr   = lane >> 2;
    const int fc   = lane & 3;

    const int m0      = blockIdx.x * 128;
    const int b       = m0 >> 12;
    const int rowbase = m0 & 4095;
    const int h0      = rowbase >> 6;

    float*   s_sum  = (float*)(smem + OFF_SUM);
    float*   s_ssq  = (float*)(smem + OFF_SSQ);
    float*   s_bias = (float*)(smem + OFF_BIAS);
    ushort4* s_co   = (ushort4*)(smem + OFF_CO);
    float4*  s_wq   = (float4*)(smem + OFF_WQ);
    uint32_t* s_Ab[2] = {(uint32_t*)(smem + OFF_A0), (uint32_t*)(smem + OFF_A1)};
    uint32_t* s_Wb[2] = {(uint32_t*)(smem + OFF_W0), (uint32_t*)(smem + OFF_W1)};

    if (tid < NC) {
        s_sum[tid] = 0.0f;
        s_ssq[tid] = 0.0f;
        s_bias[tid] = bias[tid];
    }

    // -------- phase 1: sampling metadata --------
    for (int idx = tid; idx < NKT * 128; idx += 256) {
        int kt = idx >> 7;
        int px = idx & 127;
        int h  = h0 + (px >> 6);
        int w  = px & 63;
        const float* omb = g_om + (size_t)b * NOFF * NHW;
        float offy = omb[(2 * kt) * NHW + (h << 6) + w];
        float offx = omb[(2 * kt + 1) * NHW + (h << 6) + w];
        float mv   = omb[(18 + kt) * NHW + (h << 6) + w];
        float msk  = 1.0f / (1.0f + expf(-mv));

        float py  = offy + (float)(h - 1 + kt / 3);
        float pxf = offx + (float)(w - 1 + kt % 3);
        float fy = floorf(py), fx = floorf(pxf);
        float ly = py - fy,    lx = pxf - fx;
        int y0 = (int)fy, x0 = (int)fx;
        int y1 = y0 + 1,  x1 = x0 + 1;
        float vy0 = (y0 >= 0 && y0 < NH) ? 1.0f : 0.0f;
        float vy1 = (y1 >= 0 && y1 < NH) ? 1.0f : 0.0f;
        float vx0 = (x0 >= 0 && x0 < NW) ? 1.0f : 0.0f;
        float vx1 = (x1 >= 0 && x1 < NW) ? 1.0f : 0.0f;

        float4 wq;
        wq.x = (1.0f - ly) * (1.0f - lx) * msk * vy0 * vx0;
        wq.y = (1.0f - ly) * lx          * msk * vy0 * vx1;
        wq.z = ly          * (1.0f - lx) * msk * vy1 * vx0;
        wq.w = ly          * lx          * msk * vy1 * vx1;
        s_wq[idx] = wq;

        int y0c = min(max(y0, 0), NH - 1), x0c = min(max(x0, 0), NW - 1);
        int y1c = min(max(y1, 0), NH - 1), x1c = min(max(x1, 0), NW - 1);
        ushort4 co;
        co.x = (unsigned short)(((y0c << 6) + x0c) << 2);
        co.y = (unsigned short)(((y0c << 6) + x1c) << 2);
        co.z = (unsigned short)(((y1c << 6) + x0c) << 2);
        co.w = (unsigned short)(((y1c << 6) + x1c) << 2);
        s_co[idx] = co;
    }

    float4 acc[4][4];
#pragma unroll
    for (int i = 0; i < 4; ++i)
#pragma unroll
        for (int j = 0; j < 4; ++j)
            acc[i][j] = make_float4(0.f, 0.f, 0.f, 0.f);

    const int half = tid >> 7;
    const int px   = tid & 127;

    auto fillA = [&](uint32_t* sA, int c) {
        const int kt  = c >> 2;
        const int cib = ((c & 3) << 5) + half * 16;
        const int midx = (kt << 7) + px;
        const float4  wq = s_wq[midx];
        const ushort4 co = s_co[midx];
        const char* bpx =
            (const char*)x + (((size_t)((b << 7) + cib)) << 14);
        uint32_t pk[4];
#pragma unroll
        for (int j = 0; j < 16; ++j) {
            const char* p = bpx + j * 16384;
            float v = wq.x * __ldg((const float*)(p + co.x))
                    + wq.y * __ldg((const float*)(p + co.y))
                    + wq.z * __ldg((const float*)(p + co.z))
                    + wq.w * __ldg((const float*)(p + co.w));
            pk[j & 3] = f2tf32(v);
            if ((j & 3) == 3)
                *(uint4*)(sA + px * TSTRIDE + half * 16 + (j - 3)) =
                    make_uint4(pk[0], pk[1], pk[2], pk[3]);
        }
    };
    auto fillW = [&](uint32_t* sW, int c) {
        const uint32_t* wrow = g_w2 + c * 32 + lane;
#pragma unroll
        for (int r2 = 0; r2 < 16; ++r2) {
            int o = wid * 16 + r2;
            sW[o * TSTRIDE + lane] = __ldg(wrow + o * KDIM);
        }
    };

    __syncthreads();  // phase-1 metadata ready
    fillA(s_Ab[0], 0);
    fillW(s_Wb[0], 0);
    __syncthreads();

    // -------- phase 2: 36 K-chunks, double-buffered, 1 sync/chunk --------
    for (int c = 0; c < 36; ++c) {
        const int st = c & 1;
        if (c < 35) {
            fillA(s_Ab[st ^ 1], c + 1);
            fillW(s_Wb[st ^ 1], c + 1);
        }
        const uint32_t* s_A = s_Ab[st];
        const uint32_t* s_W = s_Wb[st];
#pragma unroll
        for (int ks = 0; ks < 4; ++ks) {
            const int kb = ks * 8;
            uint32_t bfr[4][2];
#pragma unroll
            for (int j = 0; j < 4; ++j) {
                const uint32_t* wp =
                    s_W + (wc * 32 + j * 8 + fr) * TSTRIDE + kb + fc;
                bfr[j][0] = wp[0];
                bfr[j][1] = wp[4];
            }
#pragma unroll
            for (int i = 0; i < 4; ++i) {
                uint32_t afr[4];
                const uint32_t* ap =
                    s_A + (wr * 64 + i * 16 + fr) * TSTRIDE + kb + fc;
                afr[0] = ap[0];
                afr[1] = ap[8 * TSTRIDE];
                afr[2] = ap[4];
                afr[3] = ap[8 * TSTRIDE + 4];
#pragma unroll
                for (int j = 0; j < 4; ++j)
                    mma_tf32(acc[i][j], afr, bfr[j]);
            }
        }
        __syncthreads();
    }

    // -------- epilogue: bias, store y, BN partial stats --------
#pragma unroll
    for (int j = 0; j < 4; ++j) {
#pragma unroll
        for (int t = 0; t < 2; ++t) {
            int o = wc * 32 + j * 8 + 2 * fc + t;
            float bo = s_bias[o];
            float* yp = g_y + (((size_t)((b << 7) + o)) << 12) + rowbase;
            float s = 0.0f, q = 0.0f;
#pragma unroll
            for (int i = 0; i < 4; ++i) {
                float v1 = (t ? acc[i][j].y : acc[i][j].x) + bo;
                float v2 = (t ? acc[i][j].w : acc[i][j].z) + bo;
                int p1 = wr * 64 + i * 16 + fr;
                yp[p1]     = v1;
                yp[p1 + 8] = v2;
                s += v1 + v2;
                q += v1 * v1 + v2 * v2;
            }
            atomicAdd(&s_sum[o], s);
            atomicAdd(&s_ssq[o], q);
        }
    }
    __syncthreads();
    if (tid < NC) {
        atomicAdd(&g_stats[tid],      s_sum[tid]);
        atomicAdd(&g_stats[NC + tid], s_ssq[tid]);
    }
}

// ---------------------------------------------------------------------------
// Kernel D: BatchNorm (batch stats) + ReLU -> d_out
// ---------------------------------------------------------------------------
__global__ __launch_bounds__(256) void bn_relu_kernel(
    float* __restrict__ out,
    const float* __restrict__ gamma,
    const float* __restrict__ beta) {
    int idx = blockIdx.x * 256 + threadIdx.x;
    int o = (idx >> 10) & 127;
    const float invN = 1.0f / 32768.0f;
    float mean = g_stats[o] * invN;
    float var  = g_stats[NC + o] * invN - mean * mean;
    float inv  = rsqrtf(var + 1e-5f);
    float sc   = gamma[o] * inv;
    float sh   = beta[o] - mean * sc;
    float4 v = ((const float4*)g_y)[idx];
    v.x = fmaxf(fmaf(v.x, sc, sh), 0.0f);
    v.y = fmaxf(fmaf(v.y, sc, sh), 0.0f);
    v.z = fmaxf(fmaf(v.z, sc, sh), 0.0f);
    v.w = fmaxf(fmaf(v.w, sc, sh), 0.0f);
    ((float4*)out)[idx] = v;
}

// ---------------------------------------------------------------------------
extern "C" void kernel_launch(void* const* d_in, const int* in_sizes, int n_in,
                              void* d_out, int out_size) {
    const float* x     = (const float*)d_in[0];
    const float* off_w = (const float*)d_in[1];
    const float* off_b = (const float*)d_in[2];
    const float* w     = (const float*)d_in[3];
    const float* bias  = (const float*)d_in[4];
    const float* gamma = (const float*)d_in[5];
    const float* beta  = (const float*)d_in[6];
    float* out = (float*)d_out;

    cudaFuncSetAttribute(dcn_main_kernel,
                         cudaFuncAttributeMaxDynamicSharedMemorySize, SMEM_SZ);

    prep_kernel<<<144, 256>>>(w);
    off_conv_kernel<<<dim3(4, 8, 8), 256>>>(x, off_w, off_b);
    dcn_main_kernel<<<256, 256, SMEM_SZ>>>(x, bias);
    bn_relu_kernel<<<4096, 256>>>(out, gamma, beta);
}

// round 9
// speedup vs baseline: 1.0725x; 1.0725x over previous
#include <cuda_runtime.h>
#include <cuda_bf16.h>
#include <math.h>
#include <stdint.h>

// Shapes: x[8,128,64,64] off_w[27,128,3,3] off_b[27] w[128,128,3,3] b[128]
//         gamma[128] beta[128] -> out[8,128,64,64] fp32

#define NB   8
#define NC   128
#define NH   64
#define NW   64
#define NHW  4096
#define NKT  9
#define NKP  16      // padded taps
#define NOFF 27
#define KDIM 1152    // 128*9 (source weight K)
#define KPAD 2048    // 128*16 (padded GEMM K)

static __device__ float    g_om[NB * NOFF * NHW];  // offset-conv output
static __device__ uint32_t g_w2[NC * KPAD];        // w permuted [o][ci*16+kt], tf32, zero-padded
static __device__ float    g_y[NB * NC * NHW];     // pre-BN conv output
static __device__ float    g_stats[2 * NC];        // per-channel sum, sumsq

// ---------------- helpers ---------------------------------------------------
__device__ __forceinline__ uint32_t f2tf32(float v) {
    uint32_t r;
    asm("cvt.rna.tf32.f32 %0, %1;" : "=r"(r) : "f"(v));
    return r;
}
__device__ __forceinline__ void mma_tf32(float4& d, const uint32_t a[4],
                                         const uint32_t b[2]) {
    asm volatile(
        "mma.sync.aligned.m16n8k8.row.col.f32.tf32.tf32.f32 "
        "{%0,%1,%2,%3}, {%4,%5,%6,%7}, {%8,%9}, {%0,%1,%2,%3};"
        : "+f"(d.x), "+f"(d.y), "+f"(d.z), "+f"(d.w)
        : "r"(a[0]), "r"(a[1]), "r"(a[2]), "r"(a[3]), "r"(b[0]), "r"(b[1]));
}
__device__ __forceinline__ void ffma2(unsigned long long& d,
                                      unsigned long long a,
                                      unsigned long long b) {
    asm volatile("fma.rn.f32x2 %0, %1, %2, %0;" : "+l"(d) : "l"(a), "l"(b));
}
__device__ __forceinline__ unsigned long long pack2(float lo, float hi) {
    unsigned long long r;
    asm("mov.b64 %0, {%1, %2};" : "=l"(r) : "f"(lo), "f"(hi));
    return r;
}
__device__ __forceinline__ float2 unpack2(unsigned long long v) {
    float2 r;
    asm("mov.b64 {%0, %1}, %2;" : "=f"(r.x), "=f"(r.y) : "l"(v));
    return r;
}

// SMEM layout (dynamic, byte offsets). Tiles stride 36 floats (conflict-free).
#define OFF_SUM  0         // 512
#define OFF_SSQ  512       // 512
#define OFF_BIAS 1024      // 512
#define OFF_CO   1536      // 9*128*8  = 9216  (ushort4 corner byte-offsets)
#define OFF_WQ   10752     // 9*128*16 = 18432 (float4 bilinear weights)
#define OFF_A0   29184     // 128*36*4 = 18432
#define OFF_A1   47616
#define OFF_W0   66048
#define OFF_W1   84480
#define SMEM_SZ  102912
#define TSTRIDE  36

// ---------------------------------------------------------------------------
// Kernel Z: zero stats + permute weights to [o][ci*16+kt] tf32, taps 9..15 = 0
// ---------------------------------------------------------------------------
__global__ void prep_kernel(const float* __restrict__ w) {
    if (blockIdx.x == 0 && threadIdx.x < 2 * NC) g_stats[threadIdx.x] = 0.0f;
    int n = NC * KPAD;
    for (int i = blockIdx.x * blockDim.x + threadIdx.x; i < n;
         i += gridDim.x * blockDim.x) {
        int o  = i >> 11;          // / KPAD
        int r  = i & (KPAD - 1);
        int ci = r >> 4;
        int kt = r & 15;
        g_w2[i] = (kt < NKT) ? f2tf32(w[o * KDIM + ci * 9 + kt]) : 0u;
    }
}

// ---------------------------------------------------------------------------
// Kernel A: offset conv. 256 blocks (8h x 16w tiles), 4 channels / iteration.
// ---------------------------------------------------------------------------
__global__ __launch_bounds__(256) void off_conv_kernel(
    const float* __restrict__ x,
    const float* __restrict__ ow,
    const float* __restrict__ ob) {
    __shared__ float xt[4][10][18];
    __shared__ unsigned long long wdup[4 * 243];

    const int tid  = threadIdx.x;
    const int og   = tid >> 6;        // 0..3
    const int slot = tid & 63;
    const int lr   = slot >> 4;       // 0..3
    const int lc   = slot & 15;
    const int b    = blockIdx.z;
    const int by   = blockIdx.y;
    const int bx   = blockIdx.x;

    unsigned long long accp[7];
#pragma unroll
    for (int j = 0; j < 7; ++j) accp[j] = 0ull;

    for (int it = 0; it < 32; ++it) {
        const int ci0 = it << 2;
        __syncthreads();
        for (int i = tid; i < 720; i += 256) {
            int ci  = i / 180;
            int rem = i - ci * 180;
            int r   = rem / 18;
            int cp  = rem - r * 18;
            int gy  = by * 8 + r - 1;
            int gx  = bx * 16 + cp - 1;
            float v = 0.0f;
            if (gy >= 0 && gy < NH && gx >= 0 && gx < NW)
                v = __ldg(x + ((size_t)(b * NC + ci0 + ci) << 12) + (gy << 6) + gx);
            xt[ci][r][cp] = v;
        }
        for (int i = tid; i < 972; i += 256) {
            int ci  = i / 243;
            int rem = i - ci * 243;
            int o   = rem / 9;
            int t   = rem - o * 9;
            float wv = __ldg(ow + (size_t)o * KDIM + (ci0 + ci) * 9 + t);
            wdup[i] = pack2(wv, wv);
        }
        __syncthreads();

#pragma unroll
        for (int ci = 0; ci < 4; ++ci) {
            unsigned long long xp[9];
#pragma unroll
            for (int dy = 0; dy < 3; ++dy)
#pragma unroll
                for (int dx = 0; dx < 3; ++dx)
                    xp[dy * 3 + dx] = pack2(xt[ci][lr + dy][lc + dx],
                                            xt[ci][lr + 4 + dy][lc + dx]);
#pragma unroll
            for (int j = 0; j < 7; ++j) {
                int o = og * 7 + j;
                if (o < NOFF) {
#pragma unroll
                    for (int t = 0; t < 9; ++t)
                        ffma2(accp[j], xp[t], wdup[ci * 243 + o * 9 + t]);
                }
            }
        }
    }

    const int gy0 = by * 8 + lr;
    const int gx  = bx * 16 + lc;
#pragma unroll
    for (int j = 0; j < 7; ++j) {
        int o = og * 7 + j;
        if (o < NOFF) {
            float bb = __ldg(ob + o);
            float2 a = unpack2(accp[j]);
            g_om[((size_t)(b * NOFF + o) << 12) + (gy0 << 6) + gx]       = a.x + bb;
            g_om[((size_t)(b * NOFF + o) << 12) + ((gy0 + 4) << 6) + gx] = a.y + bb;
        }
    }
}

// ---------------------------------------------------------------------------
// Kernel B: deformable sampling + mma.sync tf32 implicit GEMM + BN stats.
// K = 2048 padded, ci-major: chunk c = channels {2c, 2c+1} x 16 taps.
// Per chunk the x-footprint is 2 planes (32KB) reused across 9 taps -> L1 hits.
// Double-buffered tiles, 1 sync/chunk, default occupancy (no reg cap).
// ---------------------------------------------------------------------------
__global__ __launch_bounds__(256) void dcn_main_kernel(
    const float* __restrict__ x,
    const float* __restrict__ bias) {
    extern __shared__ char smem[];
    const int tid  = threadIdx.x;
    const int wid  = tid >> 5;
    const int lane = tid & 31;
    const int wr   = wid >> 2;
    const int wc   = wid & 3;
    const int fr   = lane >> 2;
    const int fc   = lane & 3;

    const int m0      = blockIdx.x * 128;
    const int b       = m0 >> 12;
    const int rowbase = m0 & 4095;
    const int h0      = rowbase >> 6;

    float*   s_sum  = (float*)(smem + OFF_SUM);
    float*   s_ssq  = (float*)(smem + OFF_SSQ);
    float*   s_bias = (float*)(smem + OFF_BIAS);
    ushort4* s_co   = (ushort4*)(smem + OFF_CO);
    float4*  s_wq   = (float4*)(smem + OFF_WQ);
    uint32_t* s_Ab[2] = {(uint32_t*)(smem + OFF_A0), (uint32_t*)(smem + OFF_A1)};
    uint32_t* s_Wb[2] = {(uint32_t*)(smem + OFF_W0), (uint32_t*)(smem + OFF_W1)};

    if (tid < NC) {
        s_sum[tid] = 0.0f;
        s_ssq[tid] = 0.0f;
        s_bias[tid] = bias[tid];
    }

    // -------- phase 1: sampling metadata (9 real taps) --------
    for (int idx = tid; idx < NKT * 128; idx += 256) {
        int kt = idx >> 7;
        int px = idx & 127;
        int h  = h0 + (px >> 6);
        int w  = px & 63;
        const float* omb = g_om + (size_t)b * NOFF * NHW;
        float offy = omb[(2 * kt) * NHW + (h << 6) + w];
        float offx = omb[(2 * kt + 1) * NHW + (h << 6) + w];
        float mv   = omb[(18 + kt) * NHW + (h << 6) + w];
        float msk  = 1.0f / (1.0f + expf(-mv));

        float py  = offy + (float)(h - 1 + kt / 3);
        float pxf = offx + (float)(w - 1 + kt % 3);
        float fy = floorf(py), fx = floorf(pxf);
        float ly = py - fy,    lx = pxf - fx;
        int y0 = (int)fy, x0 = (int)fx;
        int y1 = y0 + 1,  x1 = x0 + 1;
        float vy0 = (y0 >= 0 && y0 < NH) ? 1.0f : 0.0f;
        float vy1 = (y1 >= 0 && y1 < NH) ? 1.0f : 0.0f;
        float vx0 = (x0 >= 0 && x0 < NW) ? 1.0f : 0.0f;
        float vx1 = (x1 >= 0 && x1 < NW) ? 1.0f : 0.0f;

        float4 wq;
        wq.x = (1.0f - ly) * (1.0f - lx) * msk * vy0 * vx0;
        wq.y = (1.0f - ly) * lx          * msk * vy0 * vx1;
        wq.z = ly          * (1.0f - lx) * msk * vy1 * vx0;
        wq.w = ly          * lx          * msk * vy1 * vx1;
        s_wq[idx] = wq;

        int y0c = min(max(y0, 0), NH - 1), x0c = min(max(x0, 0), NW - 1);
        int y1c = min(max(y1, 0), NH - 1), x1c = min(max(x1, 0), NW - 1);
        ushort4 co;
        co.x = (unsigned short)(((y0c << 6) + x0c) << 2);
        co.y = (unsigned short)(((y0c << 6) + x1c) << 2);
        co.z = (unsigned short)(((y1c << 6) + x0c) << 2);
        co.w = (unsigned short)(((y1c << 6) + x1c) << 2);
        s_co[idx] = co;
    }

    float4 acc[4][4];
#pragma unroll
    for (int i = 0; i < 4; ++i)
#pragma unroll
        for (int j = 0; j < 4; ++j)
            acc[i][j] = make_float4(0.f, 0.f, 0.f, 0.f);

    const int half = tid >> 7;   // thread's channel within the chunk pair
    const int px   = tid & 127;

    // fillA: thread covers 16 taps of channel ci = 2c + half for pixel px.
    auto fillA = [&](uint32_t* sA, int c) {
        const int ci = (c << 1) + half;
        const char* bpx = (const char*)x + (((size_t)((b << 7) + ci)) << 14);
        uint32_t* dst = sA + px * TSTRIDE + half * 16;
        uint32_t pk[4];
#pragma unroll
        for (int kt = 0; kt < 16; ++kt) {
            float v = 0.0f;
            if (kt < NKT) {
                const int midx = (kt << 7) + px;
                const float4  wq = s_wq[midx];
                const ushort4 co = s_co[midx];
                v = wq.x * __ldg((const float*)(bpx + co.x))
                  + wq.y * __ldg((const float*)(bpx + co.y))
                  + wq.z * __ldg((const float*)(bpx + co.z))
                  + wq.w * __ldg((const float*)(bpx + co.w));
            }
            pk[kt & 3] = f2tf32(v);
            if ((kt & 3) == 3)
                *(uint4*)(dst + (kt - 3)) = make_uint4(pk[0], pk[1], pk[2], pk[3]);
        }
    };
    auto fillW = [&](uint32_t* sW, int c) {
        const uint32_t* wrow = g_w2 + c * 32 + lane;
#pragma unroll
        for (int r2 = 0; r2 < 16; ++r2) {
            int o = wid * 16 + r2;
            sW[o * TSTRIDE + lane] = __ldg(wrow + o * KPAD);
        }
    };

    __syncthreads();  // phase-1 metadata ready
    fillA(s_Ab[0], 0);
    fillW(s_Wb[0], 0);
    __syncthreads();

    // -------- phase 2: 64 K-chunks, double-buffered, 1 sync/chunk --------
    for (int c = 0; c < 64; ++c) {
        const int st = c & 1;
        if (c < 63) {
            fillA(s_Ab[st ^ 1], c + 1);
            fillW(s_Wb[st ^ 1], c + 1);
        }
        const uint32_t* s_A = s_Ab[st];
        const uint32_t* s_W = s_Wb[st];
#pragma unroll
        for (int ks = 0; ks < 4; ++ks) {
            const int kb = ks * 8;
            uint32_t bfr[4][2];
#pragma unroll
            for (int j = 0; j < 4; ++j) {
                const uint32_t* wp =
                    s_W + (wc * 32 + j * 8 + fr) * TSTRIDE + kb + fc;
                bfr[j][0] = wp[0];
                bfr[j][1] = wp[4];
            }
#pragma unroll
            for (int i = 0; i < 4; ++i) {
                uint32_t afr[4];
                const uint32_t* ap =
                    s_A + (wr * 64 + i * 16 + fr) * TSTRIDE + kb + fc;
                afr[0] = ap[0];
                afr[1] = ap[8 * TSTRIDE];
                afr[2] = ap[4];
                afr[3] = ap[8 * TSTRIDE + 4];
#pragma unroll
                for (int j = 0; j < 4; ++j)
                    mma_tf32(acc[i][j], afr, bfr[j]);
            }
        }
        __syncthreads();
    }

    // -------- epilogue: bias, store y, BN partial stats --------
#pragma unroll
    for (int j = 0; j < 4; ++j) {
#pragma unroll
        for (int t = 0; t < 2; ++t) {
            int o = wc * 32 + j * 8 + 2 * fc + t;
            float bo = s_bias[o];
            float* yp = g_y + (((size_t)((b << 7) + o)) << 12) + rowbase;
            float s = 0.0f, q = 0.0f;
#pragma unroll
            for (int i = 0; i < 4; ++i) {
                float v1 = (t ? acc[i][j].y : acc[i][j].x) + bo;
                float v2 = (t ? acc[i][j].w : acc[i][j].z) + bo;
                int p1 = wr * 64 + i * 16 + fr;
                yp[p1]     = v1;
                yp[p1 + 8] = v2;
                s += v1 + v2;
                q += v1 * v1 + v2 * v2;
            }
            atomicAdd(&s_sum[o], s);
            atomicAdd(&s_ssq[o], q);
        }
    }
    __syncthreads();
    if (tid < NC) {
        atomicAdd(&g_stats[tid],      s_sum[tid]);
        atomicAdd(&g_stats[NC + tid], s_ssq[tid]);
    }
}

// ---------------------------------------------------------------------------
// Kernel D: BatchNorm (batch stats) + ReLU -> d_out
// ---------------------------------------------------------------------------
__global__ __launch_bounds__(256) void bn_relu_kernel(
    float* __restrict__ out,
    const float* __restrict__ gamma,
    const float* __restrict__ beta) {
    int idx = blockIdx.x * 256 + threadIdx.x;
    int o = (idx >> 10) & 127;
    const float invN = 1.0f / 32768.0f;
    float mean = g_stats[o] * invN;
    float var  = g_stats[NC + o] * invN - mean * mean;
    float inv  = rsqrtf(var + 1e-5f);
    float sc   = gamma[o] * inv;
    float sh   = beta[o] - mean * sc;
    float4 v = ((const float4*)g_y)[idx];
    v.x = fmaxf(fmaf(v.x, sc, sh), 0.0f);
    v.y = fmaxf(fmaf(v.y, sc, sh), 0.0f);
    v.z = fmaxf(fmaf(v.z, sc, sh), 0.0f);
    v.w = fmaxf(fmaf(v.w, sc, sh), 0.0f);
    ((float4*)out)[idx] = v;
}

// ---------------------------------------------------------------------------
extern "C" void kernel_launch(void* const* d_in, const int* in_sizes, int n_in,
                              void* d_out, int out_size) {
    const float* x     = (const float*)d_in[0];
    const float* off_w = (const float*)d_in[1];
    const float* off_b = (const float*)d_in[2];
    const float* w     = (const float*)d_in[3];
    const float* bias  = (const float*)d_in[4];
    const float* gamma = (const float*)d_in[5];
    const float* beta  = (const float*)d_in[6];
    float* out = (float*)d_out;

    cudaFuncSetAttribute(dcn_main_kernel,
                         cudaFuncAttributeMaxDynamicSharedMemorySize, SMEM_SZ);

    prep_kernel<<<144, 256>>>(w);
    off_conv_kernel<<<dim3(4, 8, 8), 256>>>(x, off_w, off_b);
    dcn_main_kernel<<<256, 256, SMEM_SZ>>>(x, bias);
    bn_relu_kernel<<<4096, 256>>>(out, gamma, beta);
}

// round 10
// speedup vs baseline: 1.3941x; 1.2999x over previous
#include <cuda_runtime.h>
#include <cuda_bf16.h>
#include <math.h>
#include <stdint.h>

// Shapes: x[8,128,64,64] off_w[27,128,3,3] off_b[27] w[128,128,3,3] b[128]
//         gamma[128] beta[128] -> out[8,128,64,64] fp32

#define NB   8
#define NC   128
#define NH   64
#define NW   64
#define NHW  4096
#define NKT  9
#define NOFF 27
#define KDIM 1152   // 128*9

static __device__ float    g_om[NB * NOFF * NHW];  // offset-conv output
static __device__ uint32_t g_w2[NC * KDIM];        // w permuted [o][kt*128+ci], tf32 bits
static __device__ float    g_y[NB * NC * NHW];     // pre-BN conv output
static __device__ float    g_stats[2 * NC];        // per-channel sum, sumsq

// ---------------- helpers ---------------------------------------------------
__device__ __forceinline__ uint32_t f2tf32(float v) {
    uint32_t r;
    asm("cvt.rna.tf32.f32 %0, %1;" : "=r"(r) : "f"(v));
    return r;
}
__device__ __forceinline__ void mma_tf32(float4& d, const uint32_t a[4],
                                         const uint32_t b[2]) {
    asm volatile(
        "mma.sync.aligned.m16n8k8.row.col.f32.tf32.tf32.f32 "
        "{%0,%1,%2,%3}, {%4,%5,%6,%7}, {%8,%9}, {%0,%1,%2,%3};"
        : "+f"(d.x), "+f"(d.y), "+f"(d.z), "+f"(d.w)
        : "r"(a[0]), "r"(a[1]), "r"(a[2]), "r"(a[3]), "r"(b[0]), "r"(b[1]));
}
__device__ __forceinline__ void ffma2(unsigned long long& d,
                                      unsigned long long a,
                                      unsigned long long b) {
    asm volatile("fma.rn.f32x2 %0, %1, %2, %0;" : "+l"(d) : "l"(a), "l"(b));
}
__device__ __forceinline__ unsigned long long pack2(float lo, float hi) {
    unsigned long long r;
    asm("mov.b64 %0, {%1, %2};" : "=l"(r) : "f"(lo), "f"(hi));
    return r;
}
__device__ __forceinline__ float2 unpack2(unsigned long long v) {
    float2 r;
    asm("mov.b64 {%0, %1}, %2;" : "=f"(r.x), "=f"(r.y) : "l"(v));
    return r;
}

// SMEM layout (byte offsets), tiles stride 36 floats (conflict-free frag LDS).
// M-tile = 64 px.
#define OFF_SUM  0         // 512
#define OFF_SSQ  512       // 512
#define OFF_BIAS 1024      // 512
#define OFF_CO   1536      // 9*64*8  = 4608 (ushort4 corner byte-offsets)
#define OFF_WQ   6144      // 9*64*16 = 9216 (float4 bilinear weights)
#define OFF_A0   15360     // 64*36*4 = 9216
#define OFF_A1   24576
#define OFF_W0   33792     // 128*36*4 = 18432
#define OFF_W1   52224
#define SMEM_SZ  70656
#define TSTRIDE  36

// ---------------------------------------------------------------------------
// Kernel Z: zero stats + permute weights to [o][kt*128+ci], tf32 bits
// ---------------------------------------------------------------------------
__global__ void prep_kernel(const float* __restrict__ w) {
    if (blockIdx.x == 0 && threadIdx.x < 2 * NC) g_stats[threadIdx.x] = 0.0f;
    int n = NC * KDIM;
    for (int i = blockIdx.x * blockDim.x + threadIdx.x; i < n;
         i += gridDim.x * blockDim.x) {
        int o  = i / KDIM;
        int r  = i - o * KDIM;
        int kt = r >> 7;
        int ci = r & 127;
        g_w2[i] = f2tf32(w[o * KDIM + ci * 9 + kt]);
    }
}

// ---------------------------------------------------------------------------
// Kernel A: offset conv. 256 blocks (8h x 16w tiles), 4 channels / iteration.
// ---------------------------------------------------------------------------
__global__ __launch_bounds__(256) void off_conv_kernel(
    const float* __restrict__ x,
    const float* __restrict__ ow,
    const float* __restrict__ ob) {
    __shared__ float xt[4][10][18];
    __shared__ unsigned long long wdup[4 * 243];

    const int tid  = threadIdx.x;
    const int og   = tid >> 6;        // 0..3
    const int slot = tid & 63;
    const int lr   = slot >> 4;       // 0..3
    const int lc   = slot & 15;
    const int b    = blockIdx.z;
    const int by   = blockIdx.y;
    const int bx   = blockIdx.x;

    unsigned long long accp[7];
#pragma unroll
    for (int j = 0; j < 7; ++j) accp[j] = 0ull;

    for (int it = 0; it < 32; ++it) {
        const int ci0 = it << 2;
        __syncthreads();
        for (int i = tid; i < 720; i += 256) {
            int ci  = i / 180;
            int rem = i - ci * 180;
            int r   = rem / 18;
            int cp  = rem - r * 18;
            int gy  = by * 8 + r - 1;
            int gx  = bx * 16 + cp - 1;
            float v = 0.0f;
            if (gy >= 0 && gy < NH && gx >= 0 && gx < NW)
                v = __ldg(x + ((size_t)(b * NC + ci0 + ci) << 12) + (gy << 6) + gx);
            xt[ci][r][cp] = v;
        }
        for (int i = tid; i < 972; i += 256) {
            int ci  = i / 243;
            int rem = i - ci * 243;
            int o   = rem / 9;
            int t   = rem - o * 9;
            float wv = __ldg(ow + (size_t)o * KDIM + (ci0 + ci) * 9 + t);
            wdup[i] = pack2(wv, wv);
        }
        __syncthreads();

#pragma unroll
        for (int ci = 0; ci < 4; ++ci) {
            unsigned long long xp[9];
#pragma unroll
            for (int dy = 0; dy < 3; ++dy)
#pragma unroll
                for (int dx = 0; dx < 3; ++dx)
                    xp[dy * 3 + dx] = pack2(xt[ci][lr + dy][lc + dx],
                                            xt[ci][lr + 4 + dy][lc + dx]);
#pragma unroll
            for (int j = 0; j < 7; ++j) {
                int o = og * 7 + j;
                if (o < NOFF) {
#pragma unroll
                    for (int t = 0; t < 9; ++t)
                        ffma2(accp[j], xp[t], wdup[ci * 243 + o * 9 + t]);
                }
            }
        }
    }

    const int gy0 = by * 8 + lr;
    const int gx  = bx * 16 + lc;
#pragma unroll
    for (int j = 0; j < 7; ++j) {
        int o = og * 7 + j;
        if (o < NOFF) {
            float bb = __ldg(ob + o);
            float2 a = unpack2(accp[j]);
            g_om[((size_t)(b * NOFF + o) << 12) + (gy0 << 6) + gx]       = a.x + bb;
            g_om[((size_t)(b * NOFF + o) << 12) + ((gy0 + 4) << 6) + gx] = a.y + bb;
        }
    }
}

// ---------------------------------------------------------------------------
// Kernel B: deformable sampling + mma.sync tf32 implicit GEMM + BN stats.
// Block tile = 64 px x 128 o (acc 32 regs/thread -> true 2 blocks/SM).
// kt-major K (k = kt*128 + ci), 36 chunks of 32, double-buffered, 1 sync/chunk.
// ---------------------------------------------------------------------------
__global__ __launch_bounds__(256, 2) void dcn_main_kernel(
    const float* __restrict__ x,
    const float* __restrict__ bias) {
    extern __shared__ char smem[];
    const int tid  = threadIdx.x;
    const int wid  = tid >> 5;
    const int lane = tid & 31;
    const int wr   = wid >> 2;   // 0..1 (M half: 32 px)
    const int wc   = wid & 3;    // 0..3 (N quarter: 32 o)
    const int fr   = lane >> 2;
    const int fc   = lane & 3;

    const int m0      = blockIdx.x * 64;
    const int b       = m0 >> 12;
    const int rowbase = m0 & 4095;
    const int h0      = rowbase >> 6;   // single image row

    float*   s_sum  = (float*)(smem + OFF_SUM);
    float*   s_ssq  = (float*)(smem + OFF_SSQ);
    float*   s_bias = (float*)(smem + OFF_BIAS);
    ushort4* s_co   = (ushort4*)(smem + OFF_CO);
    float4*  s_wq   = (float4*)(smem + OFF_WQ);
    uint32_t* s_Ab[2] = {(uint32_t*)(smem + OFF_A0), (uint32_t*)(smem + OFF_A1)};
    uint32_t* s_Wb[2] = {(uint32_t*)(smem + OFF_W0), (uint32_t*)(smem + OFF_W1)};

    if (tid < NC) {
        s_sum[tid] = 0.0f;
        s_ssq[tid] = 0.0f;
        s_bias[tid] = bias[tid];
    }

    // -------- phase 1: sampling metadata (9 taps x 64 px) --------
    for (int idx = tid; idx < NKT * 64; idx += 256) {
        int kt = idx >> 6;
        int px = idx & 63;
        int h  = h0;
        int w  = px;
        const float* omb = g_om + (size_t)b * NOFF * NHW;
        float offy = omb[(2 * kt) * NHW + (h << 6) + w];
        float offx = omb[(2 * kt + 1) * NHW + (h << 6) + w];
        float mv   = omb[(18 + kt) * NHW + (h << 6) + w];
        float msk  = 1.0f / (1.0f + expf(-mv));

        float py  = offy + (float)(h - 1 + kt / 3);
        float pxf = offx + (float)(w - 1 + kt % 3);
        float fy = floorf(py), fx = floorf(pxf);
        float ly = py - fy,    lx = pxf - fx;
        int y0 = (int)fy, x0 = (int)fx;
        int y1 = y0 + 1,  x1 = x0 + 1;
        float vy0 = (y0 >= 0 && y0 < NH) ? 1.0f : 0.0f;
        float vy1 = (y1 >= 0 && y1 < NH) ? 1.0f : 0.0f;
        float vx0 = (x0 >= 0 && x0 < NW) ? 1.0f : 0.0f;
        float vx1 = (x1 >= 0 && x1 < NW) ? 1.0f : 0.0f;

        float4 wq;
        wq.x = (1.0f - ly) * (1.0f - lx) * msk * vy0 * vx0;
        wq.y = (1.0f - ly) * lx          * msk * vy0 * vx1;
        wq.z = ly          * (1.0f - lx) * msk * vy1 * vx0;
        wq.w = ly          * lx          * msk * vy1 * vx1;
        s_wq[idx] = wq;

        int y0c = min(max(y0, 0), NH - 1), x0c = min(max(x0, 0), NW - 1);
        int y1c = min(max(y1, 0), NH - 1), x1c = min(max(x1, 0), NW - 1);
        ushort4 co;
        co.x = (unsigned short)(((y0c << 6) + x0c) << 2);
        co.y = (unsigned short)(((y0c << 6) + x1c) << 2);
        co.z = (unsigned short)(((y1c << 6) + x0c) << 2);
        co.w = (unsigned short)(((y1c << 6) + x1c) << 2);
        s_co[idx] = co;
    }

    float4 acc[2][4];
#pragma unroll
    for (int i = 0; i < 2; ++i)
#pragma unroll
        for (int j = 0; j < 4; ++j)
            acc[i][j] = make_float4(0.f, 0.f, 0.f, 0.f);

    const int quarter = tid >> 6;  // 0..3: which 8-channel span this thread fills
    const int px      = tid & 63;

    // fillA: chunk c -> tap kt=c>>2, channels ci0=(c&3)*32; this thread fills
    // 8 channels [quarter*8, quarter*8+8) for pixel px. One coord set per chunk.
    auto fillA = [&](uint32_t* sA, int c) {
        const int kt  = c >> 2;
        const int cib = ((c & 3) << 5) + (quarter << 3);
        const int midx = (kt << 6) + px;
        const float4  wq = s_wq[midx];
        const ushort4 co = s_co[midx];
        const char* bpx = (const char*)x + (((size_t)((b << 7) + cib)) << 14);
        uint32_t* dst = sA + px * TSTRIDE + (quarter << 3);
        uint32_t pk[4];
#pragma unroll
        for (int j = 0; j < 8; ++j) {
            const char* p = bpx + j * 16384;
            float v = wq.x * __ldg((const float*)(p + co.x))
                    + wq.y * __ldg((const float*)(p + co.y))
                    + wq.z * __ldg((const float*)(p + co.z))
                    + wq.w * __ldg((const float*)(p + co.w));
            pk[j & 3] = f2tf32(v);
            if ((j & 3) == 3)
                *(uint4*)(dst + (j - 3)) = make_uint4(pk[0], pk[1], pk[2], pk[3]);
        }
    };
    auto fillW = [&](uint32_t* sW, int c) {
        const uint32_t* wrow = g_w2 + c * 32 + lane;
#pragma unroll
        for (int r2 = 0; r2 < 16; ++r2) {
            int o = wid * 16 + r2;
            sW[o * TSTRIDE + lane] = __ldg(wrow + o * KDIM);
        }
    };

    __syncthreads();  // phase-1 metadata ready
    fillA(s_Ab[0], 0);
    fillW(s_Wb[0], 0);
    __syncthreads();

    // -------- phase 2: 36 K-chunks, double-buffered, 1 sync/chunk --------
    for (int c = 0; c < 36; ++c) {
        const int st = c & 1;
        if (c < 35) {
            fillA(s_Ab[st ^ 1], c + 1);
            fillW(s_Wb[st ^ 1], c + 1);
        }
        const uint32_t* s_A = s_Ab[st];
        const uint32_t* s_W = s_Wb[st];
#pragma unroll
        for (int ks = 0; ks < 4; ++ks) {
            const int kb = ks * 8;
            uint32_t bfr[4][2];
#pragma unroll
            for (int j = 0; j < 4; ++j) {
                const uint32_t* wp =
                    s_W + (wc * 32 + j * 8 + fr) * TSTRIDE + kb + fc;
                bfr[j][0] = wp[0];
                bfr[j][1] = wp[4];
            }
#pragma unroll
            for (int i = 0; i < 2; ++i) {
                uint32_t afr[4];
                const uint32_t* ap =
                    s_A + (wr * 32 + i * 16 + fr) * TSTRIDE + kb + fc;
                afr[0] = ap[0];
                afr[1] = ap[8 * TSTRIDE];
                afr[2] = ap[4];
                afr[3] = ap[8 * TSTRIDE + 4];
#pragma unroll
                for (int j = 0; j < 4; ++j)
                    mma_tf32(acc[i][j], afr, bfr[j]);
            }
        }
        __syncthreads();
    }

    // -------- epilogue: bias, store y, BN partial stats --------
#pragma unroll
    for (int j = 0; j < 4; ++j) {
#pragma unroll
        for (int t = 0; t < 2; ++t) {
            int o = wc * 32 + j * 8 + 2 * fc + t;
            float bo = s_bias[o];
            float* yp = g_y + (((size_t)((b << 7) + o)) << 12) + rowbase;
            float s = 0.0f, q = 0.0f;
#pragma unroll
            for (int i = 0; i < 2; ++i) {
                float v1 = (t ? acc[i][j].y : acc[i][j].x) + bo;
                float v2 = (t ? acc[i][j].w : acc[i][j].z) + bo;
                int p1 = wr * 32 + i * 16 + fr;
                yp[p1]     = v1;
                yp[p1 + 8] = v2;
                s += v1 + v2;
                q += v1 * v1 + v2 * v2;
            }
            atomicAdd(&s_sum[o], s);
            atomicAdd(&s_ssq[o], q);
        }
    }
    __syncthreads();
    if (tid < NC) {
        atomicAdd(&g_stats[tid],      s_sum[tid]);
        atomicAdd(&g_stats[NC + tid], s_ssq[tid]);
    }
}

// ---------------------------------------------------------------------------
// Kernel D: BatchNorm (batch stats) + ReLU -> d_out
// ---------------------------------------------------------------------------
__global__ __launch_bounds__(256) void bn_relu_kernel(
    float* __restrict__ out,
    const float* __restrict__ gamma,
    const float* __restrict__ beta) {
    int idx = blockIdx.x * 256 + threadIdx.x;
    int o = (idx >> 10) & 127;
    const float invN = 1.0f / 32768.0f;
    float mean = g_stats[o] * invN;
    float var  = g_stats[NC + o] * invN - mean * mean;
    float inv  = rsqrtf(var + 1e-5f);
    float sc   = gamma[o] * inv;
    float sh   = beta[o] - mean * sc;
    float4 v = ((const float4*)g_y)[idx];
    v.x = fmaxf(fmaf(v.x, sc, sh), 0.0f);
    v.y = fmaxf(fmaf(v.y, sc, sh), 0.0f);
    v.z = fmaxf(fmaf(v.z, sc, sh), 0.0f);
    v.w = fmaxf(fmaf(v.w, sc, sh), 0.0f);
    ((float4*)out)[idx] = v;
}

// ---------------------------------------------------------------------------
extern "C" void kernel_launch(void* const* d_in, const int* in_sizes, int n_in,
                              void* d_out, int out_size) {
    const float* x     = (const float*)d_in[0];
    const float* off_w = (const float*)d_in[1];
    const float* off_b = (const float*)d_in[2];
    const float* w     = (const float*)d_in[3];
    const float* bias  = (const float*)d_in[4];
    const float* gamma = (const float*)d_in[5];
    const float* beta  = (const float*)d_in[6];
    float* out = (float*)d_out;

    cudaFuncSetAttribute(dcn_main_kernel,
                         cudaFuncAttributeMaxDynamicSharedMemorySize, SMEM_SZ);

    prep_kernel<<<144, 256>>>(w);
    off_conv_kernel<<<dim3(4, 8, 8), 256>>>(x, off_w, off_b);
    dcn_main_kernel<<<512, 256, SMEM_SZ>>>(x, bias);
    bn_relu_kernel<<<4096, 256>>>(out, gamma, beta);
}